// round 6
// baseline (speedup 1.0000x reference)
#include <cuda_runtime.h>
#include <cuda_bf16.h>
#include <cstdint>

#define NB 8
#define SS 2048
#define DD 1024
#define AA 512
#define DVV 512

// GEMM tiling: 128x128 CTA tile, BK=32, 3-stage cp.async pipeline, swizzled smem
#define BM 128
#define BN 128
#define BKC 32
#define ROW64 64                      // bytes per smem row (32 bf16, no pad; XOR swizzle)
#define PLANE (128 * ROW64)           // 8192 B per operand plane
#define STAGE (4 * PLANE)             // 32768 B per stage
#define NSTAGE 3
#define SMEM_PIPE (NSTAGE * STAGE)    // 98304 B

// ---------------------------------------------------------------------------
// Scratch (__device__ globals; allocation-free rule)
// ---------------------------------------------------------------------------
__device__ __nv_bfloat16 g_QbHi[(size_t)NB * SS * DD];
__device__ __nv_bfloat16 g_QbLo[(size_t)NB * SS * DD];
__device__ __nv_bfloat16 g_KbHi[(size_t)NB * SS * DD];
__device__ __nv_bfloat16 g_KbLo[(size_t)NB * SS * DD];
__device__ __nv_bfloat16 g_VbHi[(size_t)NB * SS * DD];
__device__ __nv_bfloat16 g_VbLo[(size_t)NB * SS * DD];
__device__ __nv_bfloat16 g_WqHi[(size_t)AA * DD];
__device__ __nv_bfloat16 g_WqLo[(size_t)AA * DD];
__device__ __nv_bfloat16 g_WkHi[(size_t)AA * DD];
__device__ __nv_bfloat16 g_WkLo[(size_t)AA * DD];
__device__ __nv_bfloat16 g_WvHi[(size_t)DVV * DD];
__device__ __nv_bfloat16 g_WvLo[(size_t)DVV * DD];
__device__ __nv_bfloat16 g_QpHi[(size_t)NB * SS * AA];
__device__ __nv_bfloat16 g_QpLo[(size_t)NB * SS * AA];
__device__ __nv_bfloat16 g_KpHi[(size_t)NB * SS * AA];
__device__ __nv_bfloat16 g_KpLo[(size_t)NB * SS * AA];
__device__ __nv_bfloat16 g_WVTHi[(size_t)NB * DVV * SS];   // [b][v][s]
__device__ __nv_bfloat16 g_WVTLo[(size_t)NB * DVV * SS];
__device__ __nv_bfloat16 g_AtHi[(size_t)NB * SS * SS];
__device__ __nv_bfloat16 g_AtLo[(size_t)NB * SS * SS];
__device__ __nv_bfloat16 g_MkT[(size_t)NB * SS * SS];      // -1e9*mask, transposed [b][k][q]

// ---------------------------------------------------------------------------
// Helpers
// ---------------------------------------------------------------------------
__device__ __forceinline__ uint32_t smem_u32(const void* p) {
    uint32_t a;
    asm("{ .reg .u64 t; cvta.to.shared.u64 t, %1; cvt.u32.u64 %0, t; }" : "=r"(a) : "l"(p));
    return a;
}
__device__ __forceinline__ void cp16(uint32_t dst, const void* src) {
    asm volatile("cp.async.cg.shared.global [%0], [%1], 16;" :: "r"(dst), "l"(src));
}
#define CP_COMMIT() asm volatile("cp.async.commit_group;" ::: "memory")
#define CP_WAIT1()  asm volatile("cp.async.wait_group 1;" ::: "memory")
#define CP_WAIT0()  asm volatile("cp.async.wait_group 0;" ::: "memory")

__device__ __forceinline__ void ldsm4(uint32_t (&r)[4], uint32_t addr) {
    asm volatile("ldmatrix.sync.aligned.m8n8.x4.shared.b16 {%0,%1,%2,%3}, [%4];"
        : "=r"(r[0]), "=r"(r[1]), "=r"(r[2]), "=r"(r[3]) : "r"(addr));
}
__device__ __forceinline__ void mma_bf16(float* d, const uint32_t* a, uint32_t b0, uint32_t b1) {
    asm volatile("mma.sync.aligned.m16n8k16.row.col.f32.bf16.bf16.f32 "
        "{%0,%1,%2,%3}, {%4,%5,%6,%7}, {%8,%9}, {%0,%1,%2,%3};"
        : "+f"(d[0]), "+f"(d[1]), "+f"(d[2]), "+f"(d[3])
        : "r"(a[0]), "r"(a[1]), "r"(a[2]), "r"(a[3]), "r"(b0), "r"(b1));
}
__device__ __forceinline__ void split2(float a, float b, uint32_t& hi, uint32_t& lo) {
    __nv_bfloat16 ah = __float2bfloat16_rn(a);
    __nv_bfloat16 bh = __float2bfloat16_rn(b);
    __nv_bfloat16 al = __float2bfloat16_rn(a - __bfloat162float(ah));
    __nv_bfloat16 bl = __float2bfloat16_rn(b - __bfloat162float(bh));
    hi = (uint32_t)__bfloat16_as_ushort(ah) | ((uint32_t)__bfloat16_as_ushort(bh) << 16);
    lo = (uint32_t)__bfloat16_as_ushort(al) | ((uint32_t)__bfloat16_as_ushort(bl) << 16);
}

// Per-lane ldmatrix offsets (plane-relative, swizzled). [operand][ks]
struct FragOff { uint32_t a[4][2]; uint32_t b[2][2]; };
__device__ __forceinline__ void frag_offsets(int lane, int warp_m, int warp_n, FragOff& F) {
    int ha = lane >> 4;                      // A k-half (0/1)
#pragma unroll
    for (int wm = 0; wm < 4; wm++) {
        int row = warp_m * 64 + wm * 16 + (lane & 15);
        int x = (row >> 1) & 3;
#pragma unroll
        for (int ks = 0; ks < 2; ks++)
            F.a[wm][ks] = (uint32_t)(row * ROW64 + (((ks * 2 + ha) ^ x) << 4));
    }
    int rb = (lane & 7) + ((lane >> 4) << 3);
    int hb = (lane & 8) ? 1 : 0;             // B k-half
#pragma unroll
    for (int p = 0; p < 2; p++) {
        int row = warp_n * 32 + p * 16 + rb;
        int x = (row >> 1) & 3;
#pragma unroll
        for (int ks = 0; ks < 2; ks++)
            F.b[p][ks] = (uint32_t)(row * ROW64 + (((ks * 2 + hb) ^ x) << 4));
    }
}

// Issue cp.async for one BK=32 chunk into the given stage base (swizzled dst)
__device__ __forceinline__ void issue_cp(uint32_t sbase,
    const __nv_bfloat16* __restrict__ Ahi, const __nv_bfloat16* __restrict__ Alo, int lda,
    const __nv_bfloat16* __restrict__ Bhi, const __nv_bfloat16* __restrict__ Blo, int ldb,
    int k0, int tid)
{
    const int lrow = tid >> 1;
    const int c0 = (tid & 1) * 2;
    const int x = (lrow >> 1) & 3;
    const int koff = k0 + (tid & 1) * 16;
    uint32_t d0 = sbase + (uint32_t)(lrow * ROW64 + ((c0 ^ x) << 4));
    uint32_t d1 = sbase + (uint32_t)(lrow * ROW64 + (((c0 + 1) ^ x) << 4));
    const __nv_bfloat16* a0 = Ahi + (size_t)lrow * lda + koff;
    const __nv_bfloat16* a1 = Alo + (size_t)lrow * lda + koff;
    const __nv_bfloat16* b0 = Bhi + (size_t)lrow * ldb + koff;
    const __nv_bfloat16* b1 = Blo + (size_t)lrow * ldb + koff;
    cp16(d0, a0);               cp16(d1, a0 + 8);
    cp16(d0 + PLANE, a1);       cp16(d1 + PLANE, a1 + 8);
    cp16(d0 + 2 * PLANE, b0);   cp16(d1 + 2 * PLANE, b0 + 8);
    cp16(d0 + 3 * PLANE, b1);   cp16(d1 + 3 * PLANE, b1 + 8);
}

// One BK=32 chunk of bf16x3 MMA
__device__ __forceinline__ void mma_chunk32(uint32_t sb, const FragOff& F, float (*acc)[4][4]) {
#pragma unroll
    for (int ks = 0; ks < 2; ks++) {
        uint32_t af[4][4], bh[2][4], bl[2][4];
#pragma unroll
        for (int wm = 0; wm < 4; wm++) ldsm4(af[wm], sb + F.a[wm][ks]);
#pragma unroll
        for (int p = 0; p < 2; p++) ldsm4(bh[p], sb + 2 * PLANE + F.b[p][ks]);
#pragma unroll
        for (int p = 0; p < 2; p++) ldsm4(bl[p], sb + 3 * PLANE + F.b[p][ks]);
#pragma unroll
        for (int wm = 0; wm < 4; wm++)
#pragma unroll
            for (int wn = 0; wn < 4; wn++) {
                mma_bf16(acc[wm][wn], af[wm], bh[wn >> 1][(wn & 1) * 2], bh[wn >> 1][(wn & 1) * 2 + 1]);
                mma_bf16(acc[wm][wn], af[wm], bl[wn >> 1][(wn & 1) * 2], bl[wn >> 1][(wn & 1) * 2 + 1]);
            }
#pragma unroll
        for (int wm = 0; wm < 4; wm++) ldsm4(af[wm], sb + PLANE + F.a[wm][ks]);
#pragma unroll
        for (int wm = 0; wm < 4; wm++)
#pragma unroll
            for (int wn = 0; wn < 4; wn++)
                mma_bf16(acc[wm][wn], af[wm], bh[wn >> 1][(wn & 1) * 2], bh[wn >> 1][(wn & 1) * 2 + 1]);
    }
}

// 3-stage pipelined bf16 GEMM core (acc += A * B^T over K)
__device__ __forceinline__ void gemm_core(uint32_t sb,
    const __nv_bfloat16* Ahi, const __nv_bfloat16* Alo, int lda,
    const __nv_bfloat16* Bhi, const __nv_bfloat16* Blo, int ldb,
    int K, int tid, const FragOff& F, float (*acc)[4][4])
{
    const int nch = K / BKC;
    issue_cp(sb, Ahi, Alo, lda, Bhi, Blo, ldb, 0, tid);
    CP_COMMIT();
    issue_cp(sb + STAGE, Ahi, Alo, lda, Bhi, Blo, ldb, BKC, tid);
    CP_COMMIT();
    uint32_t cur = 0, nxt2 = 2 * STAGE;
    for (int ch = 0; ch < nch; ch++) {
        if (ch < nch - 1) { CP_WAIT1(); } else { CP_WAIT0(); }
        __syncthreads();
        if (ch + 2 < nch) {
            issue_cp(sb + nxt2, Ahi, Alo, lda, Bhi, Blo, ldb, (ch + 2) * BKC, tid);
            CP_COMMIT();
        }
        mma_chunk32(sb + cur, F, acc);
        cur = (cur == (NSTAGE - 1) * STAGE) ? 0 : cur + STAGE;
        nxt2 = (nxt2 == (NSTAGE - 1) * STAGE) ? 0 : nxt2 + STAGE;
    }
    __syncthreads();
}

// ---------------------------------------------------------------------------
// Fused elementwise fp32 -> bf16 hi/lo split (3 tensors via blockIdx.z)
// ---------------------------------------------------------------------------
struct SplitArgs {
    const float* in[3];
    __nv_bfloat16* hi[3];
    __nv_bfloat16* lo[3];
};
__global__ void split3_kernel(SplitArgs a, int n4)
{
    int z = blockIdx.z;
    int i = blockIdx.x * blockDim.x + threadIdx.x;
    if (i < n4) {
        float4 v = reinterpret_cast<const float4*>(a.in[z])[i];
        uint32_t h0, l0, h1, l1;
        split2(v.x, v.y, h0, l0);
        split2(v.z, v.w, h1, l1);
        reinterpret_cast<uint2*>(a.hi[z])[i] = make_uint2(h0, h1);
        reinterpret_cast<uint2*>(a.lo[z])[i] = make_uint2(l0, l1);
    }
}

// ---------------------------------------------------------------------------
// Mask transpose + prescale: mT[b][k][q] = bf16(-1e9 * mask[b][q][k])
// ---------------------------------------------------------------------------
__global__ __launch_bounds__(256)
void maskT_kernel(const int* __restrict__ mask, __nv_bfloat16* __restrict__ mT)
{
    __shared__ float t[32][33];
    const int b = blockIdx.z;
    const int q0 = blockIdx.y * 32, k0 = blockIdx.x * 32;
    const int* mb = mask + (size_t)b * SS * SS;
    __nv_bfloat16* ob = mT + (size_t)b * SS * SS;
#pragma unroll
    for (int i = 0; i < 4; i++) {
        int q = q0 + threadIdx.y + i * 8;
        t[threadIdx.y + i * 8][threadIdx.x] =
            -1e9f * (float)mb[(size_t)q * SS + k0 + threadIdx.x];
    }
    __syncthreads();
#pragma unroll
    for (int i = 0; i < 4; i++) {
        int k = k0 + threadIdx.y + i * 8;
        ob[(size_t)k * SS + q0 + threadIdx.x] =
            __float2bfloat16_rn(t[threadIdx.x][threadIdx.y + i * 8]);
    }
}

// ---------------------------------------------------------------------------
// Fused projection (Q/K/V via blockIdx.z): C = A*W^T + bias -> bf16 hi/lo.
// z==2 (V): writes WVT[b][n][s] via smem transpose.
// ---------------------------------------------------------------------------
struct ProjArgs {
    const __nv_bfloat16 *Ahi[3], *Alo[3], *Whi[3], *Wlo[3];
    const float* bias[3];
    __nv_bfloat16 *Chi[3], *Clo[3];
};
__global__ __launch_bounds__(256, 2)
void proj_kernel(ProjArgs P)
{
    extern __shared__ char smem[];
    uint32_t sb = smem_u32(smem);
    const int tid = threadIdx.x, lane = tid & 31, wid = tid >> 5;
    const int warp_m = wid & 1, warp_n = wid >> 1;
    const int m0 = blockIdx.y * BM, n0 = blockIdx.x * BN;
    const int z = blockIdx.z;
    const int transpose = (z == 2);
    const __nv_bfloat16* Ahi = P.Ahi[z];
    const __nv_bfloat16* Alo = P.Alo[z];
    const __nv_bfloat16* Whi = P.Whi[z];
    const __nv_bfloat16* Wlo = P.Wlo[z];
    const float* bias = P.bias[z];
    __nv_bfloat16* Chi = P.Chi[z];
    __nv_bfloat16* Clo = P.Clo[z];

    float acc[4][4][4];
#pragma unroll
    for (int i = 0; i < 4; i++)
#pragma unroll
        for (int j = 0; j < 4; j++)
#pragma unroll
            for (int r = 0; r < 4; r++) acc[i][j][r] = 0.f;

    FragOff F;
    frag_offsets(lane, warp_m, warp_n, F);

    gemm_core(sb, Ahi + (size_t)m0 * DD, Alo + (size_t)m0 * DD, DD,
              Whi + (size_t)n0 * DD, Wlo + (size_t)n0 * DD, DD,
              DD, tid, F, acc);

    if (!transpose) {
#pragma unroll
        for (int wn = 0; wn < 4; wn++) {
            int n = n0 + warp_n * 32 + wn * 8 + (lane & 3) * 2;
            float b0 = bias[n], b1 = bias[n + 1];
#pragma unroll
            for (int wm = 0; wm < 4; wm++)
#pragma unroll
                for (int h = 0; h < 2; h++) {
                    int m = m0 + warp_m * 64 + wm * 16 + (lane >> 2) + h * 8;
                    uint32_t hv, lv;
                    split2(acc[wm][wn][h * 2] + b0, acc[wm][wn][h * 2 + 1] + b1, hv, lv);
                    *reinterpret_cast<uint32_t*>(Chi + (size_t)m * AA + n) = hv;
                    *reinterpret_cast<uint32_t*>(Clo + (size_t)m * AA + n) = lv;
                }
        }
    } else {
        char* T = smem;   // stride 272B rows; hi plane at 0, lo plane at 34816
#pragma unroll
        for (int wn = 0; wn < 4; wn++) {
            int ln = warp_n * 32 + wn * 8 + (lane & 3) * 2;
            float b0 = bias[n0 + ln], b1 = bias[n0 + ln + 1];
#pragma unroll
            for (int wm = 0; wm < 4; wm++)
#pragma unroll
                for (int h = 0; h < 2; h++) {
                    int lm = warp_m * 64 + wm * 16 + (lane >> 2) + h * 8;
                    float v0 = acc[wm][wn][h * 2] + b0;
                    float v1 = acc[wm][wn][h * 2 + 1] + b1;
                    __nv_bfloat16 h0 = __float2bfloat16_rn(v0);
                    __nv_bfloat16 l0 = __float2bfloat16_rn(v0 - __bfloat162float(h0));
                    __nv_bfloat16 h1 = __float2bfloat16_rn(v1);
                    __nv_bfloat16 l1 = __float2bfloat16_rn(v1 - __bfloat162float(h1));
                    *reinterpret_cast<__nv_bfloat16*>(T + ln * 272 + lm * 2) = h0;
                    *reinterpret_cast<__nv_bfloat16*>(T + (ln + 1) * 272 + lm * 2) = h1;
                    *reinterpret_cast<__nv_bfloat16*>(T + 34816 + ln * 272 + lm * 2) = l0;
                    *reinterpret_cast<__nv_bfloat16*>(T + 34816 + (ln + 1) * 272 + lm * 2) = l1;
                }
        }
        __syncthreads();
        int v = tid >> 1, hs = (tid & 1) * 64;
        size_t b = (size_t)(m0 >> 11);
        int s0 = m0 & (SS - 1);
        __nv_bfloat16* dh = Chi + (b * DVV + n0 + v) * SS + s0 + hs;
        __nv_bfloat16* dl = Clo + (b * DVV + n0 + v) * SS + s0 + hs;
#pragma unroll
        for (int g = 0; g < 8; g++) {
            *reinterpret_cast<uint4*>(dh + g * 8) =
                *reinterpret_cast<uint4*>(T + v * 272 + (hs + g * 8) * 2);
            *reinterpret_cast<uint4*>(dl + g * 8) =
                *reinterpret_cast<uint4*>(T + 34816 + v * 272 + (hs + g * 8) * 2);
        }
    }
}

// ---------------------------------------------------------------------------
// Scores (pre-transposed): attn[b][k][q] = scale*Kp[k]·Qp[q] + mT[b][k][q]
// ---------------------------------------------------------------------------
__global__ __launch_bounds__(256, 2)
void scores_kernel(const __nv_bfloat16* __restrict__ KpHi, const __nv_bfloat16* __restrict__ KpLo,
                   const __nv_bfloat16* __restrict__ QpHi, const __nv_bfloat16* __restrict__ QpLo,
                   const __nv_bfloat16* __restrict__ mT, float* __restrict__ attn)
{
    extern __shared__ char smem[];
    uint32_t sb = smem_u32(smem);
    const int tid = threadIdx.x, lane = tid & 31, wid = tid >> 5;
    const int warp_m = wid & 1, warp_n = wid >> 1;
    const int m0 = blockIdx.y * BM, n0 = blockIdx.x * BN, b = blockIdx.z;

    float acc[4][4][4];
#pragma unroll
    for (int i = 0; i < 4; i++)
#pragma unroll
        for (int j = 0; j < 4; j++)
#pragma unroll
            for (int r = 0; r < 4; r++) acc[i][j][r] = 0.f;

    FragOff F;
    frag_offsets(lane, warp_m, warp_n, F);

    const size_t base = (size_t)b * SS * AA;
    gemm_core(sb, KpHi + base + (size_t)m0 * AA, KpLo + base + (size_t)m0 * AA, AA,
              QpHi + base + (size_t)n0 * AA, QpLo + base + (size_t)n0 * AA, AA,
              AA, tid, F, acc);

    const float scale = 0.04419417382415922f;   // 1/sqrt(512)
    const __nv_bfloat16* mb = mT + (size_t)b * SS * SS;
    float* ab = attn + (size_t)b * SS * SS;
#pragma unroll
    for (int wm = 0; wm < 4; wm++)
#pragma unroll
        for (int h = 0; h < 2; h++) {
            int k = m0 + warp_m * 64 + wm * 16 + (lane >> 2) + h * 8;
#pragma unroll
            for (int wn = 0; wn < 4; wn++) {
                int q = n0 + warp_n * 32 + wn * 8 + (lane & 3) * 2;
                uint32_t mu = *reinterpret_cast<const uint32_t*>(mb + (size_t)k * SS + q);
                float mv0 = __bfloat162float(__ushort_as_bfloat16((unsigned short)(mu & 0xFFFF)));
                float mv1 = __bfloat162float(__ushort_as_bfloat16((unsigned short)(mu >> 16)));
                *reinterpret_cast<float2*>(ab + (size_t)k * SS + q) =
                    make_float2(fmaf(acc[wm][wn][h * 2], scale, mv0),
                                fmaf(acc[wm][wn][h * 2 + 1], scale, mv1));
            }
        }
}

// ---------------------------------------------------------------------------
// Output: out[b][k][v] = sum_q attn[b][k][q] * WVT[b][v][q]
// ---------------------------------------------------------------------------
__global__ __launch_bounds__(256, 2)
void out_kernel(const __nv_bfloat16* __restrict__ AtHi, const __nv_bfloat16* __restrict__ AtLo,
                const __nv_bfloat16* __restrict__ WVTHi, const __nv_bfloat16* __restrict__ WVTLo,
                float* __restrict__ out)
{
    extern __shared__ char smem[];
    uint32_t sb = smem_u32(smem);
    const int tid = threadIdx.x, lane = tid & 31, wid = tid >> 5;
    const int warp_m = wid & 1, warp_n = wid >> 1;
    const int m0 = blockIdx.y * BM, n0 = blockIdx.x * BN, b = blockIdx.z;

    float acc[4][4][4];
#pragma unroll
    for (int i = 0; i < 4; i++)
#pragma unroll
        for (int j = 0; j < 4; j++)
#pragma unroll
            for (int r = 0; r < 4; r++) acc[i][j][r] = 0.f;

    FragOff F;
    frag_offsets(lane, warp_m, warp_n, F);

    const size_t abase = (size_t)b * SS * SS;
    const size_t bbase = (size_t)b * DVV * SS;
    gemm_core(sb, AtHi + abase + (size_t)m0 * SS, AtLo + abase + (size_t)m0 * SS, SS,
              WVTHi + bbase + (size_t)n0 * SS, WVTLo + bbase + (size_t)n0 * SS, SS,
              SS, tid, F, acc);

    float* ob = out + (size_t)b * SS * DVV;
#pragma unroll
    for (int wm = 0; wm < 4; wm++)
#pragma unroll
        for (int h = 0; h < 2; h++) {
            int m = m0 + warp_m * 64 + wm * 16 + (lane >> 2) + h * 8;
#pragma unroll
            for (int wn = 0; wn < 4; wn++) {
                int n = n0 + warp_n * 32 + wn * 8 + (lane & 3) * 2;
                *reinterpret_cast<float2*>(ob + (size_t)m * DVV + n) =
                    make_float2(acc[wm][wn][h * 2], acc[wm][wn][h * 2 + 1]);
            }
        }
}

// ---------------------------------------------------------------------------
// In-place row softmax (fp32) + bf16 hi/lo split write for the out GEMM.
// ---------------------------------------------------------------------------
__global__ void softmax_rows(float* __restrict__ p,
                             __nv_bfloat16* __restrict__ hi,
                             __nv_bfloat16* __restrict__ lo)
{
    __shared__ float red[33];
    size_t rb = (size_t)blockIdx.x * SS;
    float* x = p + rb;
    int tid = threadIdx.x;
    float v[8];
    float mx = -1e30f;
#pragma unroll
    for (int i = 0; i < 8; i++) { v[i] = x[tid + i * 256]; mx = fmaxf(mx, v[i]); }
#pragma unroll
    for (int o = 16; o > 0; o >>= 1) mx = fmaxf(mx, __shfl_xor_sync(0xffffffffu, mx, o));
    if ((tid & 31) == 0) red[tid >> 5] = mx;
    __syncthreads();
    if (tid < 32) {
        float m = (tid < 8) ? red[tid] : -1e30f;
#pragma unroll
        for (int o = 4; o > 0; o >>= 1) m = fmaxf(m, __shfl_xor_sync(0xffffffffu, m, o));
        if (tid == 0) red[32] = m;
    }
    __syncthreads();
    mx = red[32];
    float s = 0.f;
#pragma unroll
    for (int i = 0; i < 8; i++) { v[i] = __expf(v[i] - mx); s += v[i]; }
#pragma unroll
    for (int o = 16; o > 0; o >>= 1) s += __shfl_xor_sync(0xffffffffu, s, o);
    if ((tid & 31) == 0) red[tid >> 5] = s;
    __syncthreads();
    if (tid < 32) {
        float m = (tid < 8) ? red[tid] : 0.f;
#pragma unroll
        for (int o = 4; o > 0; o >>= 1) m += __shfl_xor_sync(0xffffffffu, m, o);
        if (tid == 0) red[32] = m;
    }
    __syncthreads();
    float inv = 1.0f / red[32];
#pragma unroll
    for (int i = 0; i < 8; i++) {
        int idx = tid + i * 256;
        float val = v[i] * inv;
        x[idx] = val;
        __nv_bfloat16 h = __float2bfloat16_rn(val);
        hi[rb + idx] = h;
        lo[rb + idx] = __float2bfloat16_rn(val - __bfloat162float(h));
    }
}

// ---------------------------------------------------------------------------
extern "C" void kernel_launch(void* const* d_in, const int* in_sizes, int n_in,
                              void* d_out, int out_size)
{
    const float* Q    = (const float*)d_in[0];
    const float* K    = (const float*)d_in[1];
    const float* V    = (const float*)d_in[2];
    const int*   mask = (const int*)  d_in[3];
    const float* Wq   = (const float*)d_in[4];
    const float* bq   = (const float*)d_in[5];
    const float* Wk   = (const float*)d_in[6];
    const float* bk   = (const float*)d_in[7];
    const float* Wv   = (const float*)d_in[8];
    const float* bv   = (const float*)d_in[9];

    float* out  = (float*)d_out;                   // selfOutput [B,S,Dv]
    float* attn = out + (size_t)NB * SS * DVV;     // attn       [B,S,S]

    static __nv_bfloat16 *pQbHi, *pQbLo, *pKbHi, *pKbLo, *pVbHi, *pVbLo;
    static __nv_bfloat16 *pWqHi, *pWqLo, *pWkHi, *pWkLo, *pWvHi, *pWvLo;
    static __nv_bfloat16 *pQpHi, *pQpLo, *pKpHi, *pKpLo, *pWVTHi, *pWVTLo;
    static __nv_bfloat16 *pAtHi, *pAtLo, *pMkT;
    static cudaStream_t s2;
    static cudaEvent_t evFork, evJoin;
    static bool inited = false;
    if (!inited) {
        cudaGetSymbolAddress((void**)&pQbHi, g_QbHi);   cudaGetSymbolAddress((void**)&pQbLo, g_QbLo);
        cudaGetSymbolAddress((void**)&pKbHi, g_KbHi);   cudaGetSymbolAddress((void**)&pKbLo, g_KbLo);
        cudaGetSymbolAddress((void**)&pVbHi, g_VbHi);   cudaGetSymbolAddress((void**)&pVbLo, g_VbLo);
        cudaGetSymbolAddress((void**)&pWqHi, g_WqHi);   cudaGetSymbolAddress((void**)&pWqLo, g_WqLo);
        cudaGetSymbolAddress((void**)&pWkHi, g_WkHi);   cudaGetSymbolAddress((void**)&pWkLo, g_WkLo);
        cudaGetSymbolAddress((void**)&pWvHi, g_WvHi);   cudaGetSymbolAddress((void**)&pWvLo, g_WvLo);
        cudaGetSymbolAddress((void**)&pQpHi, g_QpHi);   cudaGetSymbolAddress((void**)&pQpLo, g_QpLo);
        cudaGetSymbolAddress((void**)&pKpHi, g_KpHi);   cudaGetSymbolAddress((void**)&pKpLo, g_KpLo);
        cudaGetSymbolAddress((void**)&pWVTHi, g_WVTHi); cudaGetSymbolAddress((void**)&pWVTLo, g_WVTLo);
        cudaGetSymbolAddress((void**)&pAtHi, g_AtHi);   cudaGetSymbolAddress((void**)&pAtLo, g_AtLo);
        cudaGetSymbolAddress((void**)&pMkT, g_MkT);
        cudaFuncSetAttribute(proj_kernel,   cudaFuncAttributeMaxDynamicSharedMemorySize, SMEM_PIPE);
        cudaFuncSetAttribute(scores_kernel, cudaFuncAttributeMaxDynamicSharedMemorySize, SMEM_PIPE);
        cudaFuncSetAttribute(out_kernel,    cudaFuncAttributeMaxDynamicSharedMemorySize, SMEM_PIPE);
        cudaStreamCreateWithFlags(&s2, cudaStreamNonBlocking);
        cudaEventCreateWithFlags(&evFork, cudaEventDisableTiming);
        cudaEventCreateWithFlags(&evJoin, cudaEventDisableTiming);
        inited = true;
    }

    // Fork: maskT depends only on the mask input; run it on a side stream so it
    // overlaps with the splits + projections on the main (capture) stream.
    cudaEventRecord(evFork, 0);
    cudaStreamWaitEvent(s2, evFork, 0);
    maskT_kernel<<<dim3(SS / 32, SS / 32, NB), dim3(32, 8), 0, s2>>>(mask, pMkT);
    cudaEventRecord(evJoin, s2);

    // 1) Pre-split fp32 inputs to bf16 hi/lo (fused: QKV in one launch, weights in one)
    {
        SplitArgs sa;
        sa.in[0] = Q; sa.in[1] = K; sa.in[2] = V;
        sa.hi[0] = pQbHi; sa.hi[1] = pKbHi; sa.hi[2] = pVbHi;
        sa.lo[0] = pQbLo; sa.lo[1] = pKbLo; sa.lo[2] = pVbLo;
        int n4 = (NB * SS * DD) / 4;
        split3_kernel<<<dim3((n4 + 255) / 256, 1, 3), 256>>>(sa, n4);

        SplitArgs sw;
        sw.in[0] = Wq; sw.in[1] = Wk; sw.in[2] = Wv;
        sw.hi[0] = pWqHi; sw.hi[1] = pWkHi; sw.hi[2] = pWvHi;
        sw.lo[0] = pWqLo; sw.lo[1] = pWkLo; sw.lo[2] = pWvLo;
        int w4 = (AA * DD) / 4;
        split3_kernel<<<dim3((w4 + 255) / 256, 1, 3), 256>>>(sw, w4);
    }

    // 2) Fused projections (Q, K, V in one launch; z selects)
    {
        ProjArgs P;
        P.Ahi[0] = pQbHi; P.Alo[0] = pQbLo; P.Whi[0] = pWqHi; P.Wlo[0] = pWqLo;
        P.bias[0] = bq;   P.Chi[0] = pQpHi; P.Clo[0] = pQpLo;
        P.Ahi[1] = pKbHi; P.Alo[1] = pKbLo; P.Whi[1] = pWkHi; P.Wlo[1] = pWkLo;
        P.bias[1] = bk;   P.Chi[1] = pKpHi; P.Clo[1] = pKpLo;
        P.Ahi[2] = pVbHi; P.Alo[2] = pVbLo; P.Whi[2] = pWvHi; P.Wlo[2] = pWvLo;
        P.bias[2] = bv;   P.Chi[2] = pWVTHi; P.Clo[2] = pWVTLo;
        proj_kernel<<<dim3(4, 128, 3), 256, SMEM_PIPE>>>(P);
    }

    // Join: scores needs maskT output
    cudaStreamWaitEvent(0, evJoin, 0);

    // 3) Masked, pre-transposed scores -> attn (fp32, in d_out)
    scores_kernel<<<dim3(16, 16, NB), 256, SMEM_PIPE>>>(pKpHi, pKpLo, pQpHi, pQpLo, pMkT, attn);
    // 4) Row softmax in place + bf16 hi/lo side-write
    softmax_rows<<<NB * SS, 256>>>(attn, pAtHi, pAtLo);
    // 5) selfOutput = attn @ WV  (K = 2048)
    out_kernel<<<dim3(4, 16, NB), 256, SMEM_PIPE>>>(pAtHi, pAtLo, pWVTHi, pWVTLo, out);
}